// round 3
// baseline (speedup 1.0000x reference)
#include <cuda_runtime.h>

#define T_DIM 2048
#define B_DIM 4
#define E_DIM 512
#define H_DIM 8
#define BH 32          // B*H
#define HD 64
#define M0 8192        // T*B
#define N_QKV 1536     // 3*E
#define ROWSTRIDE 6144 // B_DIM * N_QKV: float stride between consecutive t (fixed b) in g_qkv

// ---- scratch (static device globals; allocation APIs are forbidden) ----
// Total static scratch: 48 + 128 + 16 = 192 MB (was 576 MB).
__device__ float g_qkv[(size_t)M0 * N_QKV];                    // 48 MB  [t*B+b, 3E]
__device__ float g_sc[(size_t)H_DIM * T_DIM * T_DIM];          // 128 MB [h, T, T] one batch-group
__device__ float g_attn[(size_t)M0 * E_DIM];                   // 16 MB  [t*B+b, E]

// ============================================================================
// Shared SGEMM body: C = A @ W^T + bias, 128x128x16 tile, 256 threads,
// 8x8 per thread (split 4+4 register tiles, conflict-free LDS.128).
// M,N multiples of 128; K multiple of 16. First `scaleCols` output columns
// are multiplied by scaleVal (q-scaling in QKV projection).
// ============================================================================
__device__ __forceinline__ void gemm_body(
    const float* __restrict__ A, const float* __restrict__ W,
    const float* __restrict__ bias, float* __restrict__ C,
    int N, int K, int scaleCols, float scaleVal)
{
    __shared__ float As[16][128];
    __shared__ float Bs[16][128];
    const int tid = threadIdx.x;
    const int tr = tid >> 4;
    const int tc = tid & 15;
    const int mBase = blockIdx.y * 128;
    const int nBase = blockIdx.x * 128;

    float acc[8][8] = {};

    for (int k0 = 0; k0 < K; k0 += 16) {
        #pragma unroll
        for (int l = 0; l < 2; ++l) {
            int idx = tid + l * 256;
            int r = idx >> 2;
            int c4 = (idx & 3) << 2;
            float4 a = *reinterpret_cast<const float4*>(A + (size_t)(mBase + r) * K + k0 + c4);
            As[c4 + 0][r] = a.x; As[c4 + 1][r] = a.y; As[c4 + 2][r] = a.z; As[c4 + 3][r] = a.w;
            float4 w = *reinterpret_cast<const float4*>(W + (size_t)(nBase + r) * K + k0 + c4);
            Bs[c4 + 0][r] = w.x; Bs[c4 + 1][r] = w.y; Bs[c4 + 2][r] = w.z; Bs[c4 + 3][r] = w.w;
        }
        __syncthreads();
        #pragma unroll
        for (int k = 0; k < 16; ++k) {
            float ra[8], rb[8];
            *reinterpret_cast<float4*>(&ra[0]) = *reinterpret_cast<float4*>(&As[k][tr * 4]);
            *reinterpret_cast<float4*>(&ra[4]) = *reinterpret_cast<float4*>(&As[k][64 + tr * 4]);
            *reinterpret_cast<float4*>(&rb[0]) = *reinterpret_cast<float4*>(&Bs[k][tc * 4]);
            *reinterpret_cast<float4*>(&rb[4]) = *reinterpret_cast<float4*>(&Bs[k][64 + tc * 4]);
            #pragma unroll
            for (int i = 0; i < 8; ++i)
                #pragma unroll
                for (int j = 0; j < 8; ++j)
                    acc[i][j] += ra[i] * rb[j];
        }
        __syncthreads();
    }

    #pragma unroll
    for (int im = 0; im < 2; ++im)
    #pragma unroll
    for (int ii = 0; ii < 4; ++ii) {
        int r = mBase + im * 64 + tr * 4 + ii;
        #pragma unroll
        for (int jn = 0; jn < 2; ++jn)
        #pragma unroll
        for (int jj = 0; jj < 4; ++jj) {
            int c = nBase + jn * 64 + tc * 4 + jj;
            float v = acc[im * 4 + ii][jn * 4 + jj] + bias[c];
            if (c < scaleCols) v *= scaleVal;
            C[(size_t)r * N + c] = v;
        }
    }
}

// QKV projection: x[M0,512] @ w_in^T + b_in -> g_qkv (q columns scaled)
__global__ __launch_bounds__(256) void qkv_kernel(
    const float* __restrict__ x, const float* __restrict__ w_in,
    const float* __restrict__ b_in)
{
    gemm_body(x, w_in, b_in, &g_qkv[0], N_QKV, E_DIM, E_DIM, 0.125f);
}

// Out projection: g_attn[M0,512] @ w_out^T + b_out -> out_attn
__global__ __launch_bounds__(256) void outproj_kernel(
    const float* __restrict__ w_out, const float* __restrict__ b_out,
    float* __restrict__ out_attn)
{
    gemm_body(&g_attn[0], w_out, b_out, out_attn, E_DIM, E_DIM, 0, 1.0f);
}

// ============================================================================
// Scores for batch-group b: for h = blockIdx.z, S[i,j] = sum_d Q[i,d]*K[j,d].
// Q row i at g_qkv + (i*B+b)*1536 + h*64; K at +512. Inner dim = 64.
// Tile 128x128x16. Grid (16,16,8).
// ============================================================================
__global__ __launch_bounds__(256) void scores_kernel(int b)
{
    __shared__ float Qs[16][128];
    __shared__ float Ks[16][128];
    const int tid = threadIdx.x;
    const int tr = tid >> 4;
    const int tc = tid & 15;
    const int h = blockIdx.z;
    const float* Qb = &g_qkv[0] + b * N_QKV + h * HD;
    const float* Kb = Qb + E_DIM;
    const int iBase = blockIdx.y * 128;
    const int jBase = blockIdx.x * 128;

    float acc[8][8] = {};

    for (int k0 = 0; k0 < HD; k0 += 16) {
        #pragma unroll
        for (int l = 0; l < 2; ++l) {
            int idx = tid + l * 256;
            int r = idx >> 2;
            int c4 = (idx & 3) << 2;
            float4 q = *reinterpret_cast<const float4*>(Qb + (size_t)(iBase + r) * ROWSTRIDE + k0 + c4);
            Qs[c4 + 0][r] = q.x; Qs[c4 + 1][r] = q.y; Qs[c4 + 2][r] = q.z; Qs[c4 + 3][r] = q.w;
            float4 kk = *reinterpret_cast<const float4*>(Kb + (size_t)(jBase + r) * ROWSTRIDE + k0 + c4);
            Ks[c4 + 0][r] = kk.x; Ks[c4 + 1][r] = kk.y; Ks[c4 + 2][r] = kk.z; Ks[c4 + 3][r] = kk.w;
        }
        __syncthreads();
        #pragma unroll
        for (int k = 0; k < 16; ++k) {
            float ra[8], rb[8];
            *reinterpret_cast<float4*>(&ra[0]) = *reinterpret_cast<float4*>(&Qs[k][tr * 4]);
            *reinterpret_cast<float4*>(&ra[4]) = *reinterpret_cast<float4*>(&Qs[k][64 + tr * 4]);
            *reinterpret_cast<float4*>(&rb[0]) = *reinterpret_cast<float4*>(&Ks[k][tc * 4]);
            *reinterpret_cast<float4*>(&rb[4]) = *reinterpret_cast<float4*>(&Ks[k][64 + tc * 4]);
            #pragma unroll
            for (int i = 0; i < 8; ++i)
                #pragma unroll
                for (int j = 0; j < 8; ++j)
                    acc[i][j] += ra[i] * rb[j];
        }
        __syncthreads();
    }

    float* S = &g_sc[0] + (size_t)h * T_DIM * T_DIM;
    #pragma unroll
    for (int im = 0; im < 2; ++im)
    #pragma unroll
    for (int ii = 0; ii < 4; ++ii) {
        int i = iBase + im * 64 + tr * 4 + ii;
        #pragma unroll
        for (int jn = 0; jn < 2; ++jn)
        #pragma unroll
        for (int jj = 0; jj < 4; ++jj) {
            int j = jBase + jn * 64 + tc * 4 + jj;
            S[(size_t)i * T_DIM + j] = acc[im * 4 + ii][jn * 4 + jj];
        }
    }
}

// ============================================================================
// Fused softmax (in place over g_sc) + head-average for batch-group b.
// One block per row i: processes the 8 head slices sequentially,
// accumulating the average in registers. Grid (2048).
// ============================================================================
__global__ __launch_bounds__(256) void softmax_avg_kernel(int b, float* __restrict__ out_avg)
{
    __shared__ float sm[8];
    const int tid = threadIdx.x;
    const int i = blockIdx.x;

    float accum[8] = {};

    for (int h = 0; h < H_DIM; ++h) {
        float* p = &g_sc[0] + ((size_t)h * T_DIM + i) * T_DIM;

        float r[8];
        #pragma unroll
        for (int j = 0; j < 8; ++j) r[j] = p[tid + j * 256];

        float m = r[0];
        #pragma unroll
        for (int j = 1; j < 8; ++j) m = fmaxf(m, r[j]);
        #pragma unroll
        for (int o = 16; o > 0; o >>= 1) m = fmaxf(m, __shfl_xor_sync(0xffffffffu, m, o));
        if ((tid & 31) == 0) sm[tid >> 5] = m;
        __syncthreads();
        m = sm[0];
        #pragma unroll
        for (int w = 1; w < 8; ++w) m = fmaxf(m, sm[w]);
        __syncthreads();

        float s = 0.f;
        #pragma unroll
        for (int j = 0; j < 8; ++j) { r[j] = __expf(r[j] - m); s += r[j]; }
        #pragma unroll
        for (int o = 16; o > 0; o >>= 1) s += __shfl_xor_sync(0xffffffffu, s, o);
        if ((tid & 31) == 0) sm[tid >> 5] = s;
        __syncthreads();
        s = 0.f;
        #pragma unroll
        for (int w = 0; w < 8; ++w) s += sm[w];

        float inv = 1.0f / s;
        #pragma unroll
        for (int j = 0; j < 8; ++j) {
            float v = r[j] * inv;
            p[tid + j * 256] = v;
            accum[j] += v;
        }
        __syncthreads();   // protect sm[] before next head's writes
    }

    float* q = out_avg + ((size_t)b * T_DIM + i) * T_DIM;
    #pragma unroll
    for (int j = 0; j < 8; ++j) q[tid + j * 256] = accum[j] * 0.125f;
}

// ============================================================================
// AV for batch-group b: per h = blockIdx.y: C[2048,64] = P[2048,2048] @ V[2048,64],
// scattered into g_attn[(i*B+b)*E + h*64 + n]. Tile 128x64x16, 8x4/thread.
// Grid (16, 8).
// ============================================================================
__global__ __launch_bounds__(256) void av_kernel(int b)
{
    __shared__ float Ws[16][128];
    __shared__ float Vs[16][64];
    const int tid = threadIdx.x;
    const int tr = tid >> 4;
    const int tc = tid & 15;
    const int h = blockIdx.y;
    const int iBase = blockIdx.x * 128;
    const float* Wmat = &g_sc[0] + (size_t)h * T_DIM * T_DIM;
    const float* Vb = &g_qkv[0] + b * N_QKV + 2 * E_DIM + h * HD;

    float acc[8][4] = {};

    for (int k0 = 0; k0 < T_DIM; k0 += 16) {
        #pragma unroll
        for (int l = 0; l < 2; ++l) {
            int idx = tid + l * 256;
            int r = idx >> 2;
            int c4 = (idx & 3) << 2;
            float4 w = *reinterpret_cast<const float4*>(Wmat + (size_t)(iBase + r) * T_DIM + k0 + c4);
            Ws[c4 + 0][r] = w.x; Ws[c4 + 1][r] = w.y; Ws[c4 + 2][r] = w.z; Ws[c4 + 3][r] = w.w;
        }
        {
            int k = tid >> 4;          // 0..15
            int n4 = (tid & 15) << 2;  // 0..60
            float4 v = *reinterpret_cast<const float4*>(Vb + (size_t)(k0 + k) * ROWSTRIDE + n4);
            *reinterpret_cast<float4*>(&Vs[k][n4]) = v;
        }
        __syncthreads();
        #pragma unroll
        for (int k = 0; k < 16; ++k) {
            float ra[8], rb[4];
            *reinterpret_cast<float4*>(&ra[0]) = *reinterpret_cast<float4*>(&Ws[k][tr * 4]);
            *reinterpret_cast<float4*>(&ra[4]) = *reinterpret_cast<float4*>(&Ws[k][64 + tr * 4]);
            *reinterpret_cast<float4*>(&rb[0]) = *reinterpret_cast<float4*>(&Vs[k][tc * 4]);
            #pragma unroll
            for (int i = 0; i < 8; ++i)
                #pragma unroll
                for (int j = 0; j < 4; ++j)
                    acc[i][j] += ra[i] * rb[j];
        }
        __syncthreads();
    }

    #pragma unroll
    for (int im = 0; im < 2; ++im)
    #pragma unroll
    for (int ii = 0; ii < 4; ++ii) {
        int i = iBase + im * 64 + tr * 4 + ii;
        #pragma unroll
        for (int jj = 0; jj < 4; ++jj) {
            int n = tc * 4 + jj;
            g_attn[((size_t)i * B_DIM + b) * E_DIM + h * HD + n] = acc[im * 4 + ii][jj];
        }
    }
}

// ============================================================================
// Host launch — kernel launches only (graph-capturable, no other APIs)
// ============================================================================
extern "C" void kernel_launch(void* const* d_in, const int* in_sizes, int n_in,
                              void* d_out, int out_size)
{
    const float* x     = (const float*)d_in[0];  // [T,B,E]
    const float* w_in  = (const float*)d_in[1];  // [3E,E]
    const float* b_in  = (const float*)d_in[2];  // [3E]
    const float* w_out = (const float*)d_in[3];  // [E,E]
    const float* b_out = (const float*)d_in[4];  // [E]

    float* out_attn = (float*)d_out;                        // [T,B,E]
    float* out_avg  = out_attn + (size_t)M0 * E_DIM;        // [B,T,T]

    // 1) QKV projection (+bias, q scaled by HD^-0.5)
    qkv_kernel<<<dim3(N_QKV / 128, M0 / 128), 256>>>(x, w_in, b_in);

    // 2) per batch-group: scores -> softmax+avg -> AV (buffer g_sc reused;
    //    stream order enforces dependencies)
    for (int b = 0; b < B_DIM; ++b) {
        scores_kernel<<<dim3(T_DIM / 128, T_DIM / 128, H_DIM), 256>>>(b);
        softmax_avg_kernel<<<dim3(T_DIM), 256>>>(b, out_avg);
        av_kernel<<<dim3(T_DIM / 128, H_DIM), 256>>>(b);
    }

    // 3) out projection (+bias) -> first output
    outproj_kernel<<<dim3(E_DIM / 128, M0 / 128), 256>>>(w_out, b_out, out_attn);
}

// round 5
// speedup vs baseline: 1.5824x; 1.5824x over previous
#include <cuda_runtime.h>
#include <cstdint>

#define T_DIM 2048
#define B_DIM 4
#define E_DIM 512
#define H_DIM 8
#define HD 64
#define M0 8192        // T*B
#define N_QKV 1536     // 3*E
#define ROWSTRIDE 6144 // B_DIM * N_QKV: float stride between consecutive t (fixed b) in g_qkv
#define SSTRIDE 132    // smem row stride (floats) for k-major operand tiles (conflict-free frags)
#define VSTRIDE 68     // smem row stride for the AV V tile

// ---- scratch (static device globals; 192 MB total — R3-proven footprint) ----
__device__ float g_qkv[(size_t)M0 * N_QKV];                    // 48 MB  [t*B+b, 3E]
__device__ float g_sc[(size_t)H_DIM * T_DIM * T_DIM];          // 128 MB [h, T, T] one batch-group
__device__ float g_attn[(size_t)M0 * E_DIM];                   // 16 MB  [t*B+b, E]

// ============================================================================
// tf32 helpers
// ============================================================================
__device__ __forceinline__ uint32_t f2tf(float f) {
    uint32_t u;
    asm("cvt.rna.tf32.f32 %0, %1;" : "=r"(u) : "f"(f));
    return u;
}

// D += A(16x8) @ B(8x8): m16n8k8 tf32, fp32 accumulate
__device__ __forceinline__ void mma8(float* c, const uint32_t* a, const uint32_t* b) {
    asm volatile(
        "mma.sync.aligned.m16n8k8.row.col.f32.tf32.tf32.f32 "
        "{%0,%1,%2,%3}, {%4,%5,%6,%7}, {%8,%9}, {%0,%1,%2,%3};\n"
        : "+f"(c[0]), "+f"(c[1]), "+f"(c[2]), "+f"(c[3])
        : "r"(a[0]), "r"(a[1]), "r"(a[2]), "r"(a[3]), "r"(b[0]), "r"(b[1]));
}

// Stage one float4 of a [rows x 32] k-contiguous gmem tile into k-major smem
// (S[k][row], row stride SSTRIDE), converting to tf32. p in [0, rows*8).
__device__ __forceinline__ void stage_frag(const float* __restrict__ src, size_t rstride,
                                           uint32_t* S, int p) {
    int r = p >> 3;
    int c4 = (p & 7) << 2;
    float4 v = *reinterpret_cast<const float4*>(src + (size_t)r * rstride + c4);
    S[(c4 + 0) * SSTRIDE + r] = f2tf(v.x);
    S[(c4 + 1) * SSTRIDE + r] = f2tf(v.y);
    S[(c4 + 2) * SSTRIDE + r] = f2tf(v.z);
    S[(c4 + 3) * SSTRIDE + r] = f2tf(v.w);
}

// Warp-level (MT*16) x 32 output tile over one staged Ktile=32.
template <int MT, int BSTRIDE>
__device__ __forceinline__ void warp_mma(const uint32_t* __restrict__ A,
                                         const uint32_t* __restrict__ B,
                                         int m0, int n0, int gid, int tig,
                                         float acc[MT][4][4]) {
    #pragma unroll
    for (int ks = 0; ks < 4; ++ks) {
        const int k = ks * 8;
        uint32_t a[MT][4], b[4][2];
        #pragma unroll
        for (int mt = 0; mt < MT; ++mt) {
            int m = m0 + mt * 16 + gid;
            a[mt][0] = A[(k + tig) * SSTRIDE + m];
            a[mt][1] = A[(k + tig) * SSTRIDE + m + 8];
            a[mt][2] = A[(k + tig + 4) * SSTRIDE + m];
            a[mt][3] = A[(k + tig + 4) * SSTRIDE + m + 8];
        }
        #pragma unroll
        for (int nt = 0; nt < 4; ++nt) {
            int n = n0 + nt * 8 + gid;
            b[nt][0] = B[(k + tig) * BSTRIDE + n];
            b[nt][1] = B[(k + tig + 4) * BSTRIDE + n];
        }
        #pragma unroll
        for (int mt = 0; mt < MT; ++mt)
            #pragma unroll
            for (int nt = 0; nt < 4; ++nt)
                mma8(acc[mt][nt], a[mt], b[nt]);
    }
}

// ============================================================================
// Projection GEMM: C[M,N] = A[M,K] @ W[N,K]^T + bias, tf32 tensor cores.
// Block 128x128, 256 threads (8 warps 2m x 4n, warp tile 64x32), Ktile 32.
// ============================================================================
__device__ __forceinline__ void gemm_tf32_body(
    const float* __restrict__ A, const float* __restrict__ W,
    const float* __restrict__ bias, float* __restrict__ C,
    int N, int K, int scaleCols, float scaleVal)
{
    __shared__ uint32_t As[32 * SSTRIDE];
    __shared__ uint32_t Bs[32 * SSTRIDE];
    const int tid = threadIdx.x;
    const int lane = tid & 31;
    const int gid = lane >> 2, tig = lane & 3;
    const int warp = tid >> 5;
    const int m0w = (warp >> 2) * 64, n0w = (warp & 3) * 32;
    const int mBase = blockIdx.y * 128, nBase = blockIdx.x * 128;

    float acc[4][4][4] = {};

    for (int k0 = 0; k0 < K; k0 += 32) {
        #pragma unroll
        for (int l = 0; l < 4; ++l) {
            stage_frag(A + (size_t)mBase * K + k0, K, As, tid + l * 256);
            stage_frag(W + (size_t)nBase * K + k0, K, Bs, tid + l * 256);
        }
        __syncthreads();
        warp_mma<4, SSTRIDE>(As, Bs, m0w, n0w, gid, tig, acc);
        __syncthreads();
    }

    #pragma unroll
    for (int mt = 0; mt < 4; ++mt) {
        int r0 = mBase + m0w + mt * 16 + gid;
        #pragma unroll
        for (int nt = 0; nt < 4; ++nt) {
            int c = nBase + n0w + nt * 8 + tig * 2;
            float b0 = bias[c], b1 = bias[c + 1];
            float2 v0 = make_float2(acc[mt][nt][0] + b0, acc[mt][nt][1] + b1);
            float2 v1 = make_float2(acc[mt][nt][2] + b0, acc[mt][nt][3] + b1);
            if (c < scaleCols) { v0.x *= scaleVal; v0.y *= scaleVal; v1.x *= scaleVal; v1.y *= scaleVal; }
            *reinterpret_cast<float2*>(C + (size_t)r0 * N + c) = v0;
            *reinterpret_cast<float2*>(C + (size_t)(r0 + 8) * N + c) = v1;
        }
    }
}

__global__ __launch_bounds__(256) void qkv_kernel(
    const float* __restrict__ x, const float* __restrict__ w_in,
    const float* __restrict__ b_in)
{
    gemm_tf32_body(x, w_in, b_in, &g_qkv[0], N_QKV, E_DIM, E_DIM, 0.125f);
}

__global__ __launch_bounds__(256) void outproj_kernel(
    const float* __restrict__ w_out, const float* __restrict__ b_out,
    float* __restrict__ out_attn)
{
    gemm_tf32_body(&g_attn[0], w_out, b_out, out_attn, E_DIM, E_DIM, 0, 1.0f);
}

// ============================================================================
// Scores for batch-group b, head h=blockIdx.z: S = Q @ K^T (q pre-scaled).
// Block 128x128, 256 thr, inner dim 64 (2 k-tiles). Grid (16,16,8).
// ============================================================================
__global__ __launch_bounds__(256) void scores_kernel(int b)
{
    __shared__ uint32_t Qs[32 * SSTRIDE];
    __shared__ uint32_t Ks[32 * SSTRIDE];
    const int tid = threadIdx.x;
    const int lane = tid & 31;
    const int gid = lane >> 2, tig = lane & 3;
    const int warp = tid >> 5;
    const int m0w = (warp >> 2) * 64, n0w = (warp & 3) * 32;
    const int h = blockIdx.z;
    const int iBase = blockIdx.y * 128, jBase = blockIdx.x * 128;
    const float* Qb = &g_qkv[0] + b * N_QKV + h * HD + (size_t)iBase * ROWSTRIDE;
    const float* Kb = &g_qkv[0] + b * N_QKV + E_DIM + h * HD + (size_t)jBase * ROWSTRIDE;

    float acc[4][4][4] = {};

    #pragma unroll
    for (int k0 = 0; k0 < HD; k0 += 32) {
        #pragma unroll
        for (int l = 0; l < 4; ++l) {
            stage_frag(Qb + k0, ROWSTRIDE, Qs, tid + l * 256);
            stage_frag(Kb + k0, ROWSTRIDE, Ks, tid + l * 256);
        }
        __syncthreads();
        warp_mma<4, SSTRIDE>(Qs, Ks, m0w, n0w, gid, tig, acc);
        __syncthreads();
    }

    float* S = &g_sc[0] + (size_t)h * T_DIM * T_DIM;
    #pragma unroll
    for (int mt = 0; mt < 4; ++mt) {
        int r0 = iBase + m0w + mt * 16 + gid;
        #pragma unroll
        for (int nt = 0; nt < 4; ++nt) {
            int c = jBase + n0w + nt * 8 + tig * 2;
            *reinterpret_cast<float2*>(S + (size_t)r0 * T_DIM + c) =
                make_float2(acc[mt][nt][0], acc[mt][nt][1]);
            *reinterpret_cast<float2*>(S + (size_t)(r0 + 8) * T_DIM + c) =
                make_float2(acc[mt][nt][2], acc[mt][nt][3]);
        }
    }
}

// ============================================================================
// Fused softmax (in place over g_sc) + head-average for batch-group b.
// One block per row i; 8 head slices sequentially. Grid (2048).
// ============================================================================
__global__ __launch_bounds__(256) void softmax_avg_kernel(int b, float* __restrict__ out_avg)
{
    __shared__ float sm[8];
    const int tid = threadIdx.x;
    const int i = blockIdx.x;

    float accum[8] = {};

    for (int h = 0; h < H_DIM; ++h) {
        float* p = &g_sc[0] + ((size_t)h * T_DIM + i) * T_DIM;

        float r[8];
        #pragma unroll
        for (int j = 0; j < 8; ++j) r[j] = p[tid + j * 256];

        float m = r[0];
        #pragma unroll
        for (int j = 1; j < 8; ++j) m = fmaxf(m, r[j]);
        #pragma unroll
        for (int o = 16; o > 0; o >>= 1) m = fmaxf(m, __shfl_xor_sync(0xffffffffu, m, o));
        if ((tid & 31) == 0) sm[tid >> 5] = m;
        __syncthreads();
        m = sm[0];
        #pragma unroll
        for (int w = 1; w < 8; ++w) m = fmaxf(m, sm[w]);
        __syncthreads();

        float s = 0.f;
        #pragma unroll
        for (int j = 0; j < 8; ++j) { r[j] = __expf(r[j] - m); s += r[j]; }
        #pragma unroll
        for (int o = 16; o > 0; o >>= 1) s += __shfl_xor_sync(0xffffffffu, s, o);
        if ((tid & 31) == 0) sm[tid >> 5] = s;
        __syncthreads();
        s = 0.f;
        #pragma unroll
        for (int w = 0; w < 8; ++w) s += sm[w];

        float inv = 1.0f / s;
        #pragma unroll
        for (int j = 0; j < 8; ++j) {
            float v = r[j] * inv;
            p[tid + j * 256] = v;
            accum[j] += v;
        }
        __syncthreads();
    }

    float* q = out_avg + ((size_t)b * T_DIM + i) * T_DIM;
    #pragma unroll
    for (int j = 0; j < 8; ++j) q[tid + j * 256] = accum[j] * 0.125f;
}

// ============================================================================
// AV for batch-group b, head h=blockIdx.y: C[2048,64] = P @ V.
// Block 64x64, 128 threads (4 warps 2x2, warp tile 32x32), Ktile 32.
// Grid (32, 8) = 256 blocks.
// ============================================================================
__global__ __launch_bounds__(128) void av_kernel(int b)
{
    __shared__ uint32_t Ps[32 * SSTRIDE];
    __shared__ uint32_t Vs[32 * VSTRIDE];
    const int tid = threadIdx.x;
    const int lane = tid & 31;
    const int gid = lane >> 2, tig = lane & 3;
    const int warp = tid >> 5;
    const int m0w = (warp >> 1) * 32, n0w = (warp & 1) * 32;
    const int h = blockIdx.y;
    const int iBase = blockIdx.x * 64;
    const float* Pm = &g_sc[0] + (size_t)h * T_DIM * T_DIM + (size_t)iBase * T_DIM;
    const float* Vb = &g_qkv[0] + b * N_QKV + 2 * E_DIM + h * HD;

    float acc[2][4][4] = {};

    for (int k0 = 0; k0 < T_DIM; k0 += 32) {
        #pragma unroll
        for (int l = 0; l < 4; ++l)
            stage_frag(Pm + k0, T_DIM, Ps, tid + l * 128);
        #pragma unroll
        for (int l = 0; l < 4; ++l) {
            int p = tid + l * 128;
            int k = p >> 4;
            int n4 = (p & 15) << 2;
            float4 v = *reinterpret_cast<const float4*>(Vb + (size_t)(k0 + k) * ROWSTRIDE + n4);
            Vs[k * VSTRIDE + n4 + 0] = f2tf(v.x);
            Vs[k * VSTRIDE + n4 + 1] = f2tf(v.y);
            Vs[k * VSTRIDE + n4 + 2] = f2tf(v.z);
            Vs[k * VSTRIDE + n4 + 3] = f2tf(v.w);
        }
        __syncthreads();
        warp_mma<2, VSTRIDE>(Ps, Vs, m0w, n0w, gid, tig, acc);
        __syncthreads();
    }

    #pragma unroll
    for (int mt = 0; mt < 2; ++mt) {
        int i0 = iBase + m0w + mt * 16 + gid;
        #pragma unroll
        for (int nt = 0; nt < 4; ++nt) {
            int n = n0w + nt * 8 + tig * 2;
            *reinterpret_cast<float2*>(&g_attn[((size_t)i0 * B_DIM + b) * E_DIM + h * HD + n]) =
                make_float2(acc[mt][nt][0], acc[mt][nt][1]);
            *reinterpret_cast<float2*>(&g_attn[((size_t)(i0 + 8) * B_DIM + b) * E_DIM + h * HD + n]) =
                make_float2(acc[mt][nt][2], acc[mt][nt][3]);
        }
    }
}

// ============================================================================
// Host launch — kernel launches only (graph-capturable)
// ============================================================================
extern "C" void kernel_launch(void* const* d_in, const int* in_sizes, int n_in,
                              void* d_out, int out_size)
{
    const float* x     = (const float*)d_in[0];  // [T,B,E]
    const float* w_in  = (const float*)d_in[1];  // [3E,E]
    const float* b_in  = (const float*)d_in[2];  // [3E]
    const float* w_out = (const float*)d_in[3];  // [E,E]
    const float* b_out = (const float*)d_in[4];  // [E]

    float* out_attn = (float*)d_out;                        // [T,B,E]
    float* out_avg  = out_attn + (size_t)M0 * E_DIM;        // [B,T,T]

    // 1) QKV projection (+bias, q scaled by HD^-0.5)
    qkv_kernel<<<dim3(N_QKV / 128, M0 / 128), 256>>>(x, w_in, b_in);

    // 2) per batch-group: scores -> softmax+avg -> AV (g_sc reused; stream order)
    for (int b = 0; b < B_DIM; ++b) {
        scores_kernel<<<dim3(T_DIM / 128, T_DIM / 128, H_DIM), 256>>>(b);
        softmax_avg_kernel<<<dim3(T_DIM), 256>>>(b, out_avg);
        av_kernel<<<dim3(T_DIM / 64, H_DIM), 128>>>(b);
    }

    // 3) out projection (+bias) -> first output
    outproj_kernel<<<dim3(E_DIM / 128, M0 / 128), 256>>>(w_out, b_out, out_attn);
}

// round 9
// speedup vs baseline: 1.8050x; 1.1407x over previous
#include <cuda_runtime.h>
#include <cstdint>

#define T_DIM 2048
#define B_DIM 4
#define E_DIM 512
#define H_DIM 8
#define HD 64
#define M0 8192        // T*B
#define N_QKV 1536     // 3*E
#define ROWSTRIDE 6144 // B_DIM * N_QKV: float stride between consecutive t (fixed b) in g_qkv
#define SSTRIDE 132    // smem row stride for k-major operand tiles (conflict-free frags)
#define VSTRIDE 68     // smem row stride for the AV V tile

// ---- scratch (static device globals; ~192 MB — proven-safe footprint) ----
__device__ float  g_qkv[(size_t)M0 * N_QKV];                   // 48 MB  [t*B+b, 3E]
__device__ float  g_sc[(size_t)H_DIM * T_DIM * T_DIM];         // 128 MB [h, T, T] raw scores, one batch-group
__device__ float  g_attn[(size_t)M0 * E_DIM];                  // 16 MB  [t*B+b, E]
__device__ float2 g_stats[H_DIM * T_DIM];                      // 128 KB (rowmax, 1/rowsum) per (h,i)

// ============================================================================
// tf32 helpers
// ============================================================================
__device__ __forceinline__ uint32_t f2tf(float f) {
    uint32_t u;
    asm("cvt.rna.tf32.f32 %0, %1;" : "=r"(u) : "f"(f));
    return u;
}

__device__ __forceinline__ void mma8(float* c, const uint32_t* a, const uint32_t* b) {
    asm volatile(
        "mma.sync.aligned.m16n8k8.row.col.f32.tf32.tf32.f32 "
        "{%0,%1,%2,%3}, {%4,%5,%6,%7}, {%8,%9}, {%0,%1,%2,%3};\n"
        : "+f"(c[0]), "+f"(c[1]), "+f"(c[2]), "+f"(c[3])
        : "r"(a[0]), "r"(a[1]), "r"(a[2]), "r"(a[3]), "r"(b[0]), "r"(b[1]));
}

// Stage one float4 of a k-contiguous gmem tile into k-major smem (S[k][row]).
__device__ __forceinline__ void stage_frag(const float* __restrict__ src, size_t rstride,
                                           uint32_t* S, int p) {
    int r = p >> 3;
    int c4 = (p & 7) << 2;
    float4 v = *reinterpret_cast<const float4*>(src + (size_t)r * rstride + c4);
    S[(c4 + 0) * SSTRIDE + r] = f2tf(v.x);
    S[(c4 + 1) * SSTRIDE + r] = f2tf(v.y);
    S[(c4 + 2) * SSTRIDE + r] = f2tf(v.z);
    S[(c4 + 3) * SSTRIDE + r] = f2tf(v.w);
}

// Warp-level (MT*16) x 32 output tile over one staged Ktile=32.
template <int MT, int BSTRIDE>
__device__ __forceinline__ void warp_mma(const uint32_t* __restrict__ A,
                                         const uint32_t* __restrict__ B,
                                         int m0, int n0, int gid, int tig,
                                         float acc[MT][4][4]) {
    #pragma unroll
    for (int ks = 0; ks < 4; ++ks) {
        const int k = ks * 8;
        uint32_t a[MT][4], b[4][2];
        #pragma unroll
        for (int mt = 0; mt < MT; ++mt) {
            int m = m0 + mt * 16 + gid;
            a[mt][0] = A[(k + tig) * SSTRIDE + m];
            a[mt][1] = A[(k + tig) * SSTRIDE + m + 8];
            a[mt][2] = A[(k + tig + 4) * SSTRIDE + m];
            a[mt][3] = A[(k + tig + 4) * SSTRIDE + m + 8];
        }
        #pragma unroll
        for (int nt = 0; nt < 4; ++nt) {
            int n = n0 + nt * 8 + gid;
            b[nt][0] = B[(k + tig) * BSTRIDE + n];
            b[nt][1] = B[(k + tig + 4) * BSTRIDE + n];
        }
        #pragma unroll
        for (int mt = 0; mt < MT; ++mt)
            #pragma unroll
            for (int nt = 0; nt < 4; ++nt)
                mma8(acc[mt][nt], a[mt], b[nt]);
    }
}

// ============================================================================
// Projection GEMM: C[M,N] = A[M,K] @ W[N,K]^T + bias (tf32). Block 128x128,
// 256 threads (8 warps 2m x 4n, warp tile 64x32), Ktile 32. Smem 33.8 KB.
// ============================================================================
__device__ __forceinline__ void gemm_tf32_body(
    const float* __restrict__ A, const float* __restrict__ W,
    const float* __restrict__ bias, float* __restrict__ C,
    int N, int K, int scaleCols, float scaleVal)
{
    __shared__ uint32_t As[32 * SSTRIDE];
    __shared__ uint32_t Bs[32 * SSTRIDE];
    const int tid = threadIdx.x;
    const int lane = tid & 31;
    const int gid = lane >> 2, tig = lane & 3;
    const int warp = tid >> 5;
    const int m0w = (warp >> 2) * 64, n0w = (warp & 3) * 32;
    const int mBase = blockIdx.y * 128, nBase = blockIdx.x * 128;

    float acc[4][4][4] = {};

    for (int k0 = 0; k0 < K; k0 += 32) {
        #pragma unroll
        for (int l = 0; l < 4; ++l) {
            stage_frag(A + (size_t)mBase * K + k0, K, As, tid + l * 256);
            stage_frag(W + (size_t)nBase * K + k0, K, Bs, tid + l * 256);
        }
        __syncthreads();
        warp_mma<4, SSTRIDE>(As, Bs, m0w, n0w, gid, tig, acc);
        __syncthreads();
    }

    #pragma unroll
    for (int mt = 0; mt < 4; ++mt) {
        int r0 = mBase + m0w + mt * 16 + gid;
        #pragma unroll
        for (int nt = 0; nt < 4; ++nt) {
            int c = nBase + n0w + nt * 8 + tig * 2;
            float b0 = bias[c], b1 = bias[c + 1];
            float2 v0 = make_float2(acc[mt][nt][0] + b0, acc[mt][nt][1] + b1);
            float2 v1 = make_float2(acc[mt][nt][2] + b0, acc[mt][nt][3] + b1);
            if (c < scaleCols) { v0.x *= scaleVal; v0.y *= scaleVal; v1.x *= scaleVal; v1.y *= scaleVal; }
            *reinterpret_cast<float2*>(C + (size_t)r0 * N + c) = v0;
            *reinterpret_cast<float2*>(C + (size_t)(r0 + 8) * N + c) = v1;
        }
    }
}

__global__ __launch_bounds__(256) void qkv_kernel(
    const float* __restrict__ x, const float* __restrict__ w_in,
    const float* __restrict__ b_in)
{
    gemm_tf32_body(x, w_in, b_in, &g_qkv[0], N_QKV, E_DIM, E_DIM, 0.125f);
}

__global__ __launch_bounds__(256) void outproj_kernel(
    const float* __restrict__ w_out, const float* __restrict__ b_out,
    float* __restrict__ out_attn)
{
    gemm_tf32_body(&g_attn[0], w_out, b_out, out_attn, E_DIM, E_DIM, 0, 1.0f);
}

// ============================================================================
// Scores (raw, q pre-scaled) for batch-group b, head h=blockIdx.z.
// Block 128x128, 256 thr. Grid (16,16,8).
// ============================================================================
__global__ __launch_bounds__(256) void scores_kernel(int b)
{
    __shared__ uint32_t Qs[32 * SSTRIDE];
    __shared__ uint32_t Ks[32 * SSTRIDE];
    const int tid = threadIdx.x;
    const int lane = tid & 31;
    const int gid = lane >> 2, tig = lane & 3;
    const int warp = tid >> 5;
    const int m0w = (warp >> 2) * 64, n0w = (warp & 3) * 32;
    const int h = blockIdx.z;
    const int iBase = blockIdx.y * 128, jBase = blockIdx.x * 128;
    const float* Qb = &g_qkv[0] + b * N_QKV + h * HD + (size_t)iBase * ROWSTRIDE;
    const float* Kb = &g_qkv[0] + b * N_QKV + E_DIM + h * HD + (size_t)jBase * ROWSTRIDE;

    float acc[4][4][4] = {};

    #pragma unroll
    for (int k0 = 0; k0 < HD; k0 += 32) {
        #pragma unroll
        for (int l = 0; l < 4; ++l) {
            stage_frag(Qb + k0, ROWSTRIDE, Qs, tid + l * 256);
            stage_frag(Kb + k0, ROWSTRIDE, Ks, tid + l * 256);
        }
        __syncthreads();
        warp_mma<4, SSTRIDE>(Qs, Ks, m0w, n0w, gid, tig, acc);
        __syncthreads();
    }

    float* S = &g_sc[0] + (size_t)h * T_DIM * T_DIM;
    #pragma unroll
    for (int mt = 0; mt < 4; ++mt) {
        int r0 = iBase + m0w + mt * 16 + gid;
        #pragma unroll
        for (int nt = 0; nt < 4; ++nt) {
            int c = jBase + n0w + nt * 8 + tig * 2;
            *reinterpret_cast<float2*>(S + (size_t)r0 * T_DIM + c) =
                make_float2(acc[mt][nt][0], acc[mt][nt][1]);
            *reinterpret_cast<float2*>(S + (size_t)(r0 + 8) * T_DIM + c) =
                make_float2(acc[mt][nt][2], acc[mt][nt][3]);
        }
    }
}

// ============================================================================
// Row stats + head-average for batch-group b. One block per row i.
// Reads RAW scores once; writes (max, 1/sum) to g_stats and the averaged
// probabilities to out_avg. No probability writeback. Grid (2048).
// ============================================================================
__global__ __launch_bounds__(256) void rowstats_avg_kernel(int b, float* __restrict__ out_avg)
{
    __shared__ float sm[8];
    const int tid = threadIdx.x;
    const int i = blockIdx.x;

    float accum[8] = {};

    for (int h = 0; h < H_DIM; ++h) {
        const float* p = &g_sc[0] + ((size_t)h * T_DIM + i) * T_DIM;

        float r[8];
        #pragma unroll
        for (int j = 0; j < 8; ++j) r[j] = p[tid + j * 256];

        float m = r[0];
        #pragma unroll
        for (int j = 1; j < 8; ++j) m = fmaxf(m, r[j]);
        #pragma unroll
        for (int o = 16; o > 0; o >>= 1) m = fmaxf(m, __shfl_xor_sync(0xffffffffu, m, o));
        if ((tid & 31) == 0) sm[tid >> 5] = m;
        __syncthreads();
        m = sm[0];
        #pragma unroll
        for (int w = 1; w < 8; ++w) m = fmaxf(m, sm[w]);
        __syncthreads();

        float s = 0.f;
        #pragma unroll
        for (int j = 0; j < 8; ++j) { r[j] = __expf(r[j] - m); s += r[j]; }
        #pragma unroll
        for (int o = 16; o > 0; o >>= 1) s += __shfl_xor_sync(0xffffffffu, s, o);
        if ((tid & 31) == 0) sm[tid >> 5] = s;
        __syncthreads();
        s = 0.f;
        #pragma unroll
        for (int w = 0; w < 8; ++w) s += sm[w];

        float inv = 1.0f / s;
        if (tid == 0) g_stats[h * T_DIM + i] = make_float2(m, inv);
        #pragma unroll
        for (int j = 0; j < 8; ++j) accum[j] += r[j] * inv;
        __syncthreads();
    }

    float* q = out_avg + ((size_t)b * T_DIM + i) * T_DIM;
    #pragma unroll
    for (int j = 0; j < 8; ++j) q[tid + j * 256] = accum[j] * 0.125f;
}

// ============================================================================
// AV for batch-group b, head h=blockIdx.y: C[2048,64] = softmax(S) @ V, with
// softmax applied on the fly from g_stats during staging.
// Block 128m x 64n, 256 threads (8 warps 4m x 2n, warp tile 32x32), Ktile 32.
// Register-prefetch, SINGLE smem buffer (26.5 KB < 48 KB), two barriers per
// k-tile: LDGs for tile t+1 in flight during mma(t). Grid (16, 8).
// ============================================================================
__global__ __launch_bounds__(256) void av_kernel(int b)
{
    __shared__ uint32_t Ps[32 * SSTRIDE];   // 16.9 KB
    __shared__ uint32_t Vs[32 * VSTRIDE];   //  8.7 KB
    __shared__ float2 sst[128];             //  1.0 KB

    const int tid = threadIdx.x;
    const int lane = tid & 31;
    const int gid = lane >> 2, tig = lane & 3;
    const int warp = tid >> 5;
    const int m0w = (warp >> 1) * 32, n0w = (warp & 1) * 32;
    const int h = blockIdx.y;
    const int iBase = blockIdx.x * 128;
    const float* Pm = &g_sc[0] + (size_t)h * T_DIM * T_DIM + (size_t)iBase * T_DIM;
    const float* Vb = &g_qkv[0] + b * N_QKV + 2 * E_DIM + h * HD;

    // row stats for this block's 128 rows
    if (tid < 128) sst[tid] = g_stats[h * T_DIM + iBase + tid];
    __syncthreads();

    float acc[2][4][4] = {};
    float4 pv[4], vv[2];

    // ---- issue LDGs for k-tile k0 into registers ----
    auto load_tiles = [&](int k0) {
        #pragma unroll
        for (int l = 0; l < 4; ++l) {
            int p = tid + l * 256;               // 128 rows x 8 float4-chunks
            int r = p >> 3, c4 = (p & 7) << 2;
            pv[l] = *reinterpret_cast<const float4*>(Pm + (size_t)r * T_DIM + k0 + c4);
        }
        #pragma unroll
        for (int l = 0; l < 2; ++l) {
            int p = tid + l * 256;               // 32 k x 16 float4-chunks
            int k = p >> 4, n4 = (p & 15) << 2;
            vv[l] = *reinterpret_cast<const float4*>(Vb + (size_t)(k0 + k) * ROWSTRIDE + n4);
        }
    };

    // ---- exp-normalize / convert + store registers into the smem buffers ----
    auto store_tiles = [&]() {
        #pragma unroll
        for (int l = 0; l < 4; ++l) {
            int p = tid + l * 256;
            int r = p >> 3, c4 = (p & 7) << 2;
            float2 st = sst[r];                  // x = rowmax, y = 1/rowsum
            float4 v = pv[l];
            Ps[(c4 + 0) * SSTRIDE + r] = f2tf(__expf(v.x - st.x) * st.y);
            Ps[(c4 + 1) * SSTRIDE + r] = f2tf(__expf(v.y - st.x) * st.y);
            Ps[(c4 + 2) * SSTRIDE + r] = f2tf(__expf(v.z - st.x) * st.y);
            Ps[(c4 + 3) * SSTRIDE + r] = f2tf(__expf(v.w - st.x) * st.y);
        }
        #pragma unroll
        for (int l = 0; l < 2; ++l) {
            int p = tid + l * 256;
            int k = p >> 4, n4 = (p & 15) << 2;
            float4 v = vv[l];
            Vs[k * VSTRIDE + n4 + 0] = f2tf(v.x);
            Vs[k * VSTRIDE + n4 + 1] = f2tf(v.y);
            Vs[k * VSTRIDE + n4 + 2] = f2tf(v.z);
            Vs[k * VSTRIDE + n4 + 3] = f2tf(v.w);
        }
    };

    // prologue: tile 0 staged
    load_tiles(0);
    store_tiles();
    __syncthreads();

    const int NT = T_DIM / 32;   // 64 k-tiles
    for (int t = 0; t < NT; ++t) {
        if (t + 1 < NT) load_tiles((t + 1) * 32);   // LDGs in flight during mma
        warp_mma<2, VSTRIDE>(Ps, Vs, m0w, n0w, gid, tig, acc);
        __syncthreads();                             // all warps done reading buffers
        if (t + 1 < NT) {
            store_tiles();
            __syncthreads();                         // stores visible before next mma
        }
    }

    #pragma unroll
    for (int mt = 0; mt < 2; ++mt) {
        int i0 = iBase + m0w + mt * 16 + gid;
        #pragma unroll
        for (int nt = 0; nt < 4; ++nt) {
            int n = n0w + nt * 8 + tig * 2;
            *reinterpret_cast<float2*>(&g_attn[((size_t)i0 * B_DIM + b) * E_DIM + h * HD + n]) =
                make_float2(acc[mt][nt][0], acc[mt][nt][1]);
            *reinterpret_cast<float2*>(&g_attn[((size_t)(i0 + 8) * B_DIM + b) * E_DIM + h * HD + n]) =
                make_float2(acc[mt][nt][2], acc[mt][nt][3]);
        }
    }
}

// ============================================================================
// Host launch — kernel launches only (graph-capturable)
// ============================================================================
extern "C" void kernel_launch(void* const* d_in, const int* in_sizes, int n_in,
                              void* d_out, int out_size)
{
    const float* x     = (const float*)d_in[0];  // [T,B,E]
    const float* w_in  = (const float*)d_in[1];  // [3E,E]
    const float* b_in  = (const float*)d_in[2];  // [3E]
    const float* w_out = (const float*)d_in[3];  // [E,E]
    const float* b_out = (const float*)d_in[4];  // [E]

    float* out_attn = (float*)d_out;                        // [T,B,E]
    float* out_avg  = out_attn + (size_t)M0 * E_DIM;        // [B,T,T]

    // 1) QKV projection (+bias, q scaled by HD^-0.5)
    qkv_kernel<<<dim3(N_QKV / 128, M0 / 128), 256>>>(x, w_in, b_in);

    // 2) per batch-group: raw scores -> row stats + avg -> AV (softmax fused)
    for (int b = 0; b < B_DIM; ++b) {
        scores_kernel<<<dim3(T_DIM / 128, T_DIM / 128, H_DIM), 256>>>(b);
        rowstats_avg_kernel<<<dim3(T_DIM), 256>>>(b, out_avg);
        av_kernel<<<dim3(T_DIM / 128, H_DIM), 256>>>(b);
    }

    // 3) out projection (+bias) -> first output
    outproj_kernel<<<dim3(E_DIM / 128, M0 / 128), 256>>>(w_out, b_out, out_attn);
}

// round 10
// speedup vs baseline: 1.8255x; 1.0114x over previous
#include <cuda_runtime.h>
#include <cstdint>

#define T_DIM 2048
#define B_DIM 4
#define E_DIM 512
#define H_DIM 8
#define HD 64
#define M0 8192        // T*B
#define N_QKV 1536     // 3*E
#define ROWSTRIDE 6144 // B_DIM * N_QKV: float stride between consecutive t (fixed b) in g_qkv
#define SSTRIDE 132    // smem row stride for k-major operand tiles (conflict-free frags)
#define VSTRIDE 68     // smem row stride for the AV V tile

// ---- scratch (static device globals; ~192 MB — proven-safe footprint) ----
__device__ float g_qkv[(size_t)M0 * N_QKV];                   // 48 MB  [t*B+b, 3E]
__device__ float g_sc[(size_t)H_DIM * T_DIM * T_DIM];         // 128 MB [h, T, T] scores->probs, one batch-group
__device__ float g_attn[(size_t)M0 * E_DIM];                  // 16 MB  [t*B+b, E]

// ============================================================================
// tf32 helpers
// ============================================================================
__device__ __forceinline__ uint32_t f2tf(float f) {
    uint32_t u;
    asm("cvt.rna.tf32.f32 %0, %1;" : "=r"(u) : "f"(f));
    return u;
}

__device__ __forceinline__ void mma8(float* c, const uint32_t* a, const uint32_t* b) {
    asm volatile(
        "mma.sync.aligned.m16n8k8.row.col.f32.tf32.tf32.f32 "
        "{%0,%1,%2,%3}, {%4,%5,%6,%7}, {%8,%9}, {%0,%1,%2,%3};\n"
        : "+f"(c[0]), "+f"(c[1]), "+f"(c[2]), "+f"(c[3])
        : "r"(a[0]), "r"(a[1]), "r"(a[2]), "r"(a[3]), "r"(b[0]), "r"(b[1]));
}

// Stage one float4 of a k-contiguous gmem tile into k-major smem (S[k][row]).
__device__ __forceinline__ void stage_frag(const float* __restrict__ src, size_t rstride,
                                           uint32_t* S, int p) {
    int r = p >> 3;
    int c4 = (p & 7) << 2;
    float4 v = *reinterpret_cast<const float4*>(src + (size_t)r * rstride + c4);
    S[(c4 + 0) * SSTRIDE + r] = f2tf(v.x);
    S[(c4 + 1) * SSTRIDE + r] = f2tf(v.y);
    S[(c4 + 2) * SSTRIDE + r] = f2tf(v.z);
    S[(c4 + 3) * SSTRIDE + r] = f2tf(v.w);
}

// Warp-level (MT*16) x 32 output tile over one staged Ktile=32.
template <int MT, int BSTRIDE>
__device__ __forceinline__ void warp_mma(const uint32_t* __restrict__ A,
                                         const uint32_t* __restrict__ B,
                                         int m0, int n0, int gid, int tig,
                                         float acc[MT][4][4]) {
    #pragma unroll
    for (int ks = 0; ks < 4; ++ks) {
        const int k = ks * 8;
        uint32_t a[MT][4], b[4][2];
        #pragma unroll
        for (int mt = 0; mt < MT; ++mt) {
            int m = m0 + mt * 16 + gid;
            a[mt][0] = A[(k + tig) * SSTRIDE + m];
            a[mt][1] = A[(k + tig) * SSTRIDE + m + 8];
            a[mt][2] = A[(k + tig + 4) * SSTRIDE + m];
            a[mt][3] = A[(k + tig + 4) * SSTRIDE + m + 8];
        }
        #pragma unroll
        for (int nt = 0; nt < 4; ++nt) {
            int n = n0 + nt * 8 + gid;
            b[nt][0] = B[(k + tig) * BSTRIDE + n];
            b[nt][1] = B[(k + tig + 4) * BSTRIDE + n];
        }
        #pragma unroll
        for (int mt = 0; mt < MT; ++mt)
            #pragma unroll
            for (int nt = 0; nt < 4; ++nt)
                mma8(acc[mt][nt], a[mt], b[nt]);
    }
}

// ============================================================================
// Projection GEMM: C[M,N] = A[M,K] @ W[N,K]^T + bias (tf32). Block 128x128,
// 256 threads (8 warps 2m x 4n, warp tile 64x32), Ktile 32. Smem 33.8 KB.
// ============================================================================
__device__ __forceinline__ void gemm_tf32_body(
    const float* __restrict__ A, const float* __restrict__ W,
    const float* __restrict__ bias, float* __restrict__ C,
    int N, int K, int scaleCols, float scaleVal)
{
    __shared__ uint32_t As[32 * SSTRIDE];
    __shared__ uint32_t Bs[32 * SSTRIDE];
    const int tid = threadIdx.x;
    const int lane = tid & 31;
    const int gid = lane >> 2, tig = lane & 3;
    const int warp = tid >> 5;
    const int m0w = (warp >> 2) * 64, n0w = (warp & 3) * 32;
    const int mBase = blockIdx.y * 128, nBase = blockIdx.x * 128;

    float acc[4][4][4] = {};

    for (int k0 = 0; k0 < K; k0 += 32) {
        #pragma unroll
        for (int l = 0; l < 4; ++l) {
            stage_frag(A + (size_t)mBase * K + k0, K, As, tid + l * 256);
            stage_frag(W + (size_t)nBase * K + k0, K, Bs, tid + l * 256);
        }
        __syncthreads();
        warp_mma<4, SSTRIDE>(As, Bs, m0w, n0w, gid, tig, acc);
        __syncthreads();
    }

    #pragma unroll
    for (int mt = 0; mt < 4; ++mt) {
        int r0 = mBase + m0w + mt * 16 + gid;
        #pragma unroll
        for (int nt = 0; nt < 4; ++nt) {
            int c = nBase + n0w + nt * 8 + tig * 2;
            float b0 = bias[c], b1 = bias[c + 1];
            float2 v0 = make_float2(acc[mt][nt][0] + b0, acc[mt][nt][1] + b1);
            float2 v1 = make_float2(acc[mt][nt][2] + b0, acc[mt][nt][3] + b1);
            if (c < scaleCols) { v0.x *= scaleVal; v0.y *= scaleVal; v1.x *= scaleVal; v1.y *= scaleVal; }
            *reinterpret_cast<float2*>(C + (size_t)r0 * N + c) = v0;
            *reinterpret_cast<float2*>(C + (size_t)(r0 + 8) * N + c) = v1;
        }
    }
}

__global__ __launch_bounds__(256) void qkv_kernel(
    const float* __restrict__ x, const float* __restrict__ w_in,
    const float* __restrict__ b_in)
{
    gemm_tf32_body(x, w_in, b_in, &g_qkv[0], N_QKV, E_DIM, E_DIM, 0.125f);
}

__global__ __launch_bounds__(256) void outproj_kernel(
    const float* __restrict__ w_out, const float* __restrict__ b_out,
    float* __restrict__ out_attn)
{
    gemm_tf32_body(&g_attn[0], w_out, b_out, out_attn, E_DIM, E_DIM, 0, 1.0f);
}

// ============================================================================
// Scores (raw, q pre-scaled) for batch-group b, head h=blockIdx.z.
// Block 128x128, 256 thr. Grid (16,16,8).
// ============================================================================
__global__ __launch_bounds__(256) void scores_kernel(int b)
{
    __shared__ uint32_t Qs[32 * SSTRIDE];
    __shared__ uint32_t Ks[32 * SSTRIDE];
    const int tid = threadIdx.x;
    const int lane = tid & 31;
    const int gid = lane >> 2, tig = lane & 3;
    const int warp = tid >> 5;
    const int m0w = (warp >> 2) * 64, n0w = (warp & 3) * 32;
    const int h = blockIdx.z;
    const int iBase = blockIdx.y * 128, jBase = blockIdx.x * 128;
    const float* Qb = &g_qkv[0] + b * N_QKV + h * HD + (size_t)iBase * ROWSTRIDE;
    const float* Kb = &g_qkv[0] + b * N_QKV + E_DIM + h * HD + (size_t)jBase * ROWSTRIDE;

    float acc[4][4][4] = {};

    #pragma unroll
    for (int k0 = 0; k0 < HD; k0 += 32) {
        #pragma unroll
        for (int l = 0; l < 4; ++l) {
            stage_frag(Qb + k0, ROWSTRIDE, Qs, tid + l * 256);
            stage_frag(Kb + k0, ROWSTRIDE, Ks, tid + l * 256);
        }
        __syncthreads();
        warp_mma<4, SSTRIDE>(Qs, Ks, m0w, n0w, gid, tig, acc);
        __syncthreads();
    }

    float* S = &g_sc[0] + (size_t)h * T_DIM * T_DIM;
    #pragma unroll
    for (int mt = 0; mt < 4; ++mt) {
        int r0 = iBase + m0w + mt * 16 + gid;
        #pragma unroll
        for (int nt = 0; nt < 4; ++nt) {
            int c = jBase + n0w + nt * 8 + tig * 2;
            *reinterpret_cast<float2*>(S + (size_t)r0 * T_DIM + c) =
                make_float2(acc[mt][nt][0], acc[mt][nt][1]);
            *reinterpret_cast<float2*>(S + (size_t)(r0 + 8) * T_DIM + c) =
                make_float2(acc[mt][nt][2], acc[mt][nt][3]);
        }
    }
}

// ============================================================================
// Fused softmax (in place over g_sc) + head-average for batch-group b.
// One block per row i; 8 head slices sequentially. exp computed exactly once,
// chip-wide (2048 blocks), probabilities written back for av. Grid (2048).
// ============================================================================
__global__ __launch_bounds__(256) void softmax_avg_kernel(int b, float* __restrict__ out_avg)
{
    __shared__ float sm[8];
    const int tid = threadIdx.x;
    const int i = blockIdx.x;

    float accum[8] = {};

    for (int h = 0; h < H_DIM; ++h) {
        float* p = &g_sc[0] + ((size_t)h * T_DIM + i) * T_DIM;

        float r[8];
        #pragma unroll
        for (int j = 0; j < 8; ++j) r[j] = p[tid + j * 256];

        float m = r[0];
        #pragma unroll
        for (int j = 1; j < 8; ++j) m = fmaxf(m, r[j]);
        #pragma unroll
        for (int o = 16; o > 0; o >>= 1) m = fmaxf(m, __shfl_xor_sync(0xffffffffu, m, o));
        if ((tid & 31) == 0) sm[tid >> 5] = m;
        __syncthreads();
        m = sm[0];
        #pragma unroll
        for (int w = 1; w < 8; ++w) m = fmaxf(m, sm[w]);
        __syncthreads();

        float s = 0.f;
        #pragma unroll
        for (int j = 0; j < 8; ++j) { r[j] = __expf(r[j] - m); s += r[j]; }
        #pragma unroll
        for (int o = 16; o > 0; o >>= 1) s += __shfl_xor_sync(0xffffffffu, s, o);
        if ((tid & 31) == 0) sm[tid >> 5] = s;
        __syncthreads();
        s = 0.f;
        #pragma unroll
        for (int w = 0; w < 8; ++w) s += sm[w];

        float inv = 1.0f / s;
        #pragma unroll
        for (int j = 0; j < 8; ++j) {
            float v = r[j] * inv;
            p[tid + j * 256] = v;      // probability writeback (read by av)
            accum[j] += v;
        }
        __syncthreads();
    }

    float* q = out_avg + ((size_t)b * T_DIM + i) * T_DIM;
    #pragma unroll
    for (int j = 0; j < 8; ++j) q[tid + j * 256] = accum[j] * 0.125f;
}

// ============================================================================
// AV for batch-group b, head h=blockIdx.y: C[2048,64] = P @ V, P = probs.
// Block 128m x 64n, 256 threads (8 warps 4m x 2n, warp tile 32x32), Ktile 32.
// Register-prefetch, single smem buffer (25.6 KB), two barriers per k-tile;
// staging is pure cvt (no exp — removed the MUFU bottleneck). Grid (16, 8).
// ============================================================================
__global__ __launch_bounds__(256) void av_kernel(int b)
{
    __shared__ uint32_t Ps[32 * SSTRIDE];   // 16.9 KB
    __shared__ uint32_t Vs[32 * VSTRIDE];   //  8.7 KB

    const int tid = threadIdx.x;
    const int lane = tid & 31;
    const int gid = lane >> 2, tig = lane & 3;
    const int warp = tid >> 5;
    const int m0w = (warp >> 1) * 32, n0w = (warp & 1) * 32;
    const int h = blockIdx.y;
    const int iBase = blockIdx.x * 128;
    const float* Pm = &g_sc[0] + (size_t)h * T_DIM * T_DIM + (size_t)iBase * T_DIM;
    const float* Vb = &g_qkv[0] + b * N_QKV + 2 * E_DIM + h * HD;

    float acc[2][4][4] = {};
    float4 pv[4], vv[2];

    auto load_tiles = [&](int k0) {
        #pragma unroll
        for (int l = 0; l < 4; ++l) {
            int p = tid + l * 256;               // 128 rows x 8 float4-chunks
            int r = p >> 3, c4 = (p & 7) << 2;
            pv[l] = *reinterpret_cast<const float4*>(Pm + (size_t)r * T_DIM + k0 + c4);
        }
        #pragma unroll
        for (int l = 0; l < 2; ++l) {
            int p = tid + l * 256;               // 32 k x 16 float4-chunks
            int k = p >> 4, n4 = (p & 15) << 2;
            vv[l] = *reinterpret_cast<const float4*>(Vb + (size_t)(k0 + k) * ROWSTRIDE + n4);
        }
    };

    auto store_tiles = [&]() {
        #pragma unroll
        for (int l = 0; l < 4; ++l) {
            int p = tid + l * 256;
            int r = p >> 3, c4 = (p & 7) << 2;
            float4 v = pv[l];
            Ps[(c4 + 0) * SSTRIDE + r] = f2tf(v.x);
            Ps[(c4 + 1) * SSTRIDE + r] = f2tf(v.y);
            Ps[(c4 + 2) * SSTRIDE + r] = f2tf(v.z);
            Ps[(c4 + 3) * SSTRIDE + r] = f2tf(v.w);
        }
        #pragma unroll
        for (int l = 0; l < 2; ++l) {
            int p = tid + l * 256;
            int k = p >> 4, n4 = (p & 15) << 2;
            float4 v = vv[l];
            Vs[k * VSTRIDE + n4 + 0] = f2tf(v.x);
            Vs[k * VSTRIDE + n4 + 1] = f2tf(v.y);
            Vs[k * VSTRIDE + n4 + 2] = f2tf(v.z);
            Vs[k * VSTRIDE + n4 + 3] = f2tf(v.w);
        }
    };

    load_tiles(0);
    store_tiles();
    __syncthreads();

    const int NT = T_DIM / 32;   // 64 k-tiles
    for (int t = 0; t < NT; ++t) {
        if (t + 1 < NT) load_tiles((t + 1) * 32);   // LDGs in flight during mma
        warp_mma<2, VSTRIDE>(Ps, Vs, m0w, n0w, gid, tig, acc);
        __syncthreads();
        if (t + 1 < NT) {
            store_tiles();
            __syncthreads();
        }
    }

    #pragma unroll
    for (int mt = 0; mt < 2; ++mt) {
        int i0 = iBase + m0w + mt * 16 + gid;
        #pragma unroll
        for (int nt = 0; nt < 4; ++nt) {
            int n = n0w + nt * 8 + tig * 2;
            *reinterpret_cast<float2*>(&g_attn[((size_t)i0 * B_DIM + b) * E_DIM + h * HD + n]) =
                make_float2(acc[mt][nt][0], acc[mt][nt][1]);
            *reinterpret_cast<float2*>(&g_attn[((size_t)(i0 + 8) * B_DIM + b) * E_DIM + h * HD + n]) =
                make_float2(acc[mt][nt][2], acc[mt][nt][3]);
        }
    }
}

// ============================================================================
// Host launch — kernel launches only (graph-capturable)
// ============================================================================
extern "C" void kernel_launch(void* const* d_in, const int* in_sizes, int n_in,
                              void* d_out, int out_size)
{
    const float* x     = (const float*)d_in[0];  // [T,B,E]
    const float* w_in  = (const float*)d_in[1];  // [3E,E]
    const float* b_in  = (const float*)d_in[2];  // [3E]
    const float* w_out = (const float*)d_in[3];  // [E,E]
    const float* b_out = (const float*)d_in[4];  // [E]

    float* out_attn = (float*)d_out;                        // [T,B,E]
    float* out_avg  = out_attn + (size_t)M0 * E_DIM;        // [B,T,T]

    // 1) QKV projection (+bias, q scaled by HD^-0.5)
    qkv_kernel<<<dim3(N_QKV / 128, M0 / 128), 256>>>(x, w_in, b_in);

    // 2) per batch-group: scores -> softmax(writeback)+avg -> AV
    for (int b = 0; b < B_DIM; ++b) {
        scores_kernel<<<dim3(T_DIM / 128, T_DIM / 128, H_DIM), 256>>>(b);
        softmax_avg_kernel<<<dim3(T_DIM), 256>>>(b, out_avg);
        av_kernel<<<dim3(T_DIM / 128, H_DIM), 256>>>(b);
    }

    // 3) out projection (+bias) -> first output
    outproj_kernel<<<dim3(E_DIM / 128, M0 / 128), 256>>>(w_out, b_out, out_attn);
}